// round 10
// baseline (speedup 1.0000x reference)
#include <cuda_runtime.h>
#include <cuda_bf16.h>
#include <cstdint>

// Problem constants
#define D_MODEL 768
#define D_INNER 768
#define D_STATE 8
#define BATCH   4
#define SEQ     8192
#define M_TOT   (BATCH * SEQ)        // 32768
#define N_IN    (2 * D_INNER)        // 1536
#define KDIM    768
#define CHUNK   32
#define NCHUNK  (SEQ / CHUNK)        // 256

// Scratch (static __device__ arrays per allocation rules)
__device__ float g_XZ[(size_t)M_TOT * N_IN];             // x @ W_in (fp32)
__device__ float g_YZ[(size_t)M_TOT * D_INNER];          // tf32-rounded y*silu(z)
__device__ float g_Wr[(size_t)D_MODEL * N_IN + (size_t)D_INNER * D_MODEL]; // rounded W_in | W_out
__device__ float g_CS[(size_t)BATCH * NCHUNK * D_INNER]; // chunk sums / offsets

// ---------------------------------------------------------------------------
// tf32 helpers
// ---------------------------------------------------------------------------
__device__ __forceinline__ float to_tf32(float x) {
    uint32_t r;
    asm("cvt.rna.tf32.f32 %0, %1;" : "=r"(r) : "f"(x));
    return __uint_as_float(r);
}
__device__ __forceinline__ uint32_t tf32_bits(float x) {
    uint32_t r;
    asm("cvt.rna.tf32.f32 %0, %1;" : "=r"(r) : "f"(x));
    return r;
}

__global__ __launch_bounds__(256) void round_tf32_kernel(
    const float* __restrict__ in, float* __restrict__ out, int n4)
{
    int i = blockIdx.x * blockDim.x + threadIdx.x;
    if (i >= n4) return;
    float4 v = ((const float4*)in)[i];
    v.x = to_tf32(v.x); v.y = to_tf32(v.y); v.z = to_tf32(v.z); v.w = to_tf32(v.w);
    ((float4*)out)[i] = v;
}

// ---------------------------------------------------------------------------
// TF32 tensor-core GEMM: 128x128 blocktile, BK=32, 2-stage cp.async ring,
// 3 CTAs/SM. 256 threads = 8 warps (4m x 2n); warp tile 32x64; mma.m16n8k8.
// ROUND_A rounds A fragments in registers (A may be raw fp32).
// ---------------------------------------------------------------------------
#define BM 128
#define BN 128
#define BKT 32
#define STAGES 2
#define ASTRIDE 36   // 32 + 4 pad
#define BSTRIDE 136  // 128 + 8 pad
#define A_STAGE_F (BM * ASTRIDE)            // 4608 floats
#define B_STAGE_F (BKT * BSTRIDE)           // 4352 floats
#define GEMM_SMEM_BYTES ((STAGES * (A_STAGE_F + B_STAGE_F)) * 4)  // 71680

__device__ __forceinline__ void mma_tf32(float* d, const uint32_t* a, const uint32_t* b) {
    asm volatile(
        "mma.sync.aligned.m16n8k8.row.col.f32.tf32.tf32.f32 "
        "{%0,%1,%2,%3}, {%4,%5,%6,%7}, {%8,%9}, {%0,%1,%2,%3};\n"
        : "+f"(d[0]), "+f"(d[1]), "+f"(d[2]), "+f"(d[3])
        : "r"(a[0]), "r"(a[1]), "r"(a[2]), "r"(a[3]), "r"(b[0]), "r"(b[1]));
}

__device__ __forceinline__ void cpa16(void* dst, const void* src) {
    unsigned d = (unsigned)__cvta_generic_to_shared(dst);
    asm volatile("cp.async.cg.shared.global [%0], [%1], 16;" :: "r"(d), "l"(src) : "memory");
}

template<bool ROUND_A>
__global__ __launch_bounds__(256, 3) void gemm_tf32_kernel(
    const float* __restrict__ A, const float* __restrict__ B,
    float* __restrict__ C, int M, int N, int K)
{
    extern __shared__ float smem[];
    float* Asm = smem;                          // [STAGES][BM][ASTRIDE]
    float* Bsm = smem + STAGES * A_STAGE_F;     // [STAGES][BKT][BSTRIDE]

    const int tid  = threadIdx.x;
    const int lane = tid & 31;
    const int wid  = tid >> 5;
    const int wm   = wid >> 1;   // 0..3
    const int wn   = wid & 1;    // 0..1
    const int bm   = blockIdx.y;
    const int bn   = blockIdx.x;

    const float* Ab = A + (size_t)bm * BM * K;
    const float* Bb = B + (size_t)bn * BN;

    float acc[2][8][4];
    #pragma unroll
    for (int mi = 0; mi < 2; mi++)
        #pragma unroll
        for (int ni = 0; ni < 8; ni++)
            #pragma unroll
            for (int q = 0; q < 4; q++) acc[mi][ni][q] = 0.0f;

    const int NT = K / BKT;   // 24

    auto load_stage = [&](int kt, int st) {
        float* As = Asm + st * A_STAGE_F;
        float* Bs = Bsm + st * B_STAGE_F;
        const int k0 = kt * BKT;
        // A tile 128x32 floats = 1024 float4
        #pragma unroll
        for (int i = 0; i < 4; i++) {
            const int idx = tid + i * 256;
            const int r = idx >> 3, c4 = (idx & 7) << 2;
            cpa16(&As[r * ASTRIDE + c4], Ab + (size_t)r * K + k0 + c4);
        }
        // B tile 32x128 floats = 1024 float4
        #pragma unroll
        for (int i = 0; i < 4; i++) {
            const int idx = tid + i * 256;
            const int r = idx >> 5, c4 = (idx & 31) << 2;
            cpa16(&Bs[r * BSTRIDE + c4], Bb + (size_t)(k0 + r) * N + c4);
        }
        asm volatile("cp.async.commit_group;" ::: "memory");
    };

    load_stage(0, 0);

    for (int kt = 0; kt < NT; kt++) {
        asm volatile("cp.async.wait_group 0;" ::: "memory");
        __syncthreads();   // stage kt ready; prior compute on buf^1 done

        if (kt + 1 < NT) load_stage(kt + 1, (kt + 1) & 1);

        const float* As = Asm + (kt & 1) * A_STAGE_F;
        const float* Bs = Bsm + (kt & 1) * B_STAGE_F;

        #pragma unroll
        for (int ks = 0; ks < BKT; ks += 8) {
            uint32_t afr[2][4];
            #pragma unroll
            for (int mi = 0; mi < 2; mi++) {
                const int r = wm * 32 + mi * 16 + (lane >> 2);
                const int c = ks + (lane & 3);
                float a0 = As[r * ASTRIDE + c];
                float a1 = As[(r + 8) * ASTRIDE + c];
                float a2 = As[r * ASTRIDE + c + 4];
                float a3 = As[(r + 8) * ASTRIDE + c + 4];
                if (ROUND_A) {
                    afr[mi][0] = tf32_bits(a0); afr[mi][1] = tf32_bits(a1);
                    afr[mi][2] = tf32_bits(a2); afr[mi][3] = tf32_bits(a3);
                } else {
                    afr[mi][0] = __float_as_uint(a0); afr[mi][1] = __float_as_uint(a1);
                    afr[mi][2] = __float_as_uint(a2); afr[mi][3] = __float_as_uint(a3);
                }
            }
            uint32_t bfr[8][2];
            #pragma unroll
            for (int ni = 0; ni < 8; ni++) {
                const int kk = ks + (lane & 3);
                const int n  = wn * 64 + ni * 8 + (lane >> 2);
                bfr[ni][0] = __float_as_uint(Bs[kk * BSTRIDE + n]);
                bfr[ni][1] = __float_as_uint(Bs[(kk + 4) * BSTRIDE + n]);
            }
            #pragma unroll
            for (int mi = 0; mi < 2; mi++)
                #pragma unroll
                for (int ni = 0; ni < 8; ni++)
                    mma_tf32(acc[mi][ni], afr[mi], bfr[ni]);
        }
    }

    float* Cb = C + (size_t)bm * BM * N + (size_t)bn * BN;
    #pragma unroll
    for (int mi = 0; mi < 2; mi++) {
        #pragma unroll
        for (int ni = 0; ni < 8; ni++) {
            const int r = wm * 32 + mi * 16 + (lane >> 2);
            const int c = wn * 64 + ni * 8 + ((lane & 3) << 1);
            *(float2*)&Cb[(size_t)r * N + c] =
                make_float2(acc[mi][ni][0], acc[mi][ni][1]);
            *(float2*)&Cb[(size_t)(r + 8) * N + c] =
                make_float2(acc[mi][ni][2], acc[mi][ni][3]);
        }
    }
}

// ---------------------------------------------------------------------------
// silu helper
// ---------------------------------------------------------------------------
__device__ __forceinline__ float silu_f(float v) {
    return v / (1.0f + __expf(-v));
}

// ---------------------------------------------------------------------------
// Pass A: per-chunk sums of u = silu(conv3(xc)+bias). 4 channels per thread.
// ---------------------------------------------------------------------------
__global__ __launch_bounds__(192) void scan_partial_kernel(
    const float* __restrict__ xz,
    const float* __restrict__ convw, const float* __restrict__ convb,
    float* __restrict__ csum)
{
    const int tq = threadIdx.x;
    const int chunk = blockIdx.x;
    const int b = blockIdx.y;
    const int t0 = chunk * CHUNK;
    const int c0 = tq * 4;

    float w0[4], w1[4], w2[4], cb[4];
    #pragma unroll
    for (int j = 0; j < 4; j++) {
        w0[j] = convw[(c0 + j) * 3 + 0];
        w1[j] = convw[(c0 + j) * 3 + 1];
        w2[j] = convw[(c0 + j) * 3 + 2];
        cb[j] = convb[c0 + j];
    }

    const float* p = xz + ((size_t)b * SEQ + t0) * N_IN + c0;

    float4 xm2 = make_float4(0, 0, 0, 0), xm1 = make_float4(0, 0, 0, 0);
    if (t0 >= 2) {
        xm2 = *(const float4*)(p - 2 * N_IN);
        xm1 = *(const float4*)(p - 1 * N_IN);
    }

    float s[4] = {0, 0, 0, 0};
    #pragma unroll 8
    for (int t = 0; t < CHUNK; t++) {
        float4 x0 = *(const float4*)(p + (size_t)t * N_IN);
        float m2[4] = {xm2.x, xm2.y, xm2.z, xm2.w};
        float m1[4] = {xm1.x, xm1.y, xm1.z, xm1.w};
        float cc[4] = {x0.x, x0.y, x0.z, x0.w};
        #pragma unroll
        for (int j = 0; j < 4; j++) {
            float v = fmaf(w0[j], m2[j], fmaf(w1[j], m1[j], fmaf(w2[j], cc[j], cb[j])));
            s[j] += silu_f(v);
        }
        xm2 = xm1; xm1 = x0;
    }
    *(float4*)&csum[((size_t)b * NCHUNK + chunk) * D_INNER + c0] =
        make_float4(s[0], s[1], s[2], s[3]);
}

// ---------------------------------------------------------------------------
// Pass B: block-parallel exclusive scan over NCHUNK chunk sums.
// ---------------------------------------------------------------------------
__global__ __launch_bounds__(NCHUNK) void scan_offsets_kernel(float* __restrict__ csum)
{
    __shared__ float4 sh[NCHUNK];
    const int k = threadIdx.x;
    const int c0 = blockIdx.x * 4;
    const int b = blockIdx.y;

    float4* ptr = (float4*)&csum[((size_t)b * NCHUNK + k) * D_INNER + c0];
    float4 v = *ptr;
    sh[k] = v;
    __syncthreads();

    #pragma unroll
    for (int off = 1; off < NCHUNK; off <<= 1) {
        float4 t = make_float4(0, 0, 0, 0);
        const bool has = (k >= off);
        if (has) t = sh[k - off];
        __syncthreads();
        if (has) {
            v.x += t.x; v.y += t.y; v.z += t.z; v.w += t.w;
            sh[k] = v;
        }
        __syncthreads();
    }
    float4 ex = (k > 0) ? sh[k - 1] : make_float4(0, 0, 0, 0);
    *ptr = ex;
}

// ---------------------------------------------------------------------------
// Pass C: recompute u, y = cum*BC + u*D, times silu(z); write tf32-rounded.
// ---------------------------------------------------------------------------
__global__ __launch_bounds__(192) void scan_apply_kernel(
    const float* __restrict__ xz,
    const float* __restrict__ convw, const float* __restrict__ convb,
    const float* __restrict__ Bm, const float* __restrict__ Cm,
    const float* __restrict__ Dv,
    const float* __restrict__ csum,
    float* __restrict__ yz)
{
    const int tq = threadIdx.x;
    const int chunk = blockIdx.x;
    const int b = blockIdx.y;
    const int t0 = chunk * CHUNK;
    const int c0 = tq * 4;

    float w0[4], w1[4], w2[4], cb[4], bc[4], dd[4];
    #pragma unroll
    for (int j = 0; j < 4; j++) {
        w0[j] = convw[(c0 + j) * 3 + 0];
        w1[j] = convw[(c0 + j) * 3 + 1];
        w2[j] = convw[(c0 + j) * 3 + 2];
        cb[j] = convb[c0 + j];
        float acc = 0.0f;
        #pragma unroll
        for (int s = 0; s < D_STATE; s++)
            acc = fmaf(Bm[(c0 + j) * D_STATE + s], Cm[(c0 + j) * D_STATE + s], acc);
        bc[j] = acc;
        dd[j] = Dv[c0 + j];
    }

    const float* p = xz + ((size_t)b * SEQ + t0) * N_IN + c0;
    float* q = yz + ((size_t)b * SEQ + t0) * D_INNER + c0;

    float4 xm2 = make_float4(0, 0, 0, 0), xm1 = make_float4(0, 0, 0, 0);
    if (t0 >= 2) {
        xm2 = *(const float4*)(p - 2 * N_IN);
        xm1 = *(const float4*)(p - 1 * N_IN);
    }

    float4 runv = *(const float4*)&csum[((size_t)b * NCHUNK + chunk) * D_INNER + c0];
    float run[4] = {runv.x, runv.y, runv.z, runv.w};

    #pragma unroll 8
    for (int t = 0; t < CHUNK; t++) {
        float4 x0 = *(const float4*)(p + (size_t)t * N_IN);
        float4 zz = *(const float4*)(p + (size_t)t * N_IN + D_INNER);
        float m2[4] = {xm2.x, xm2.y, xm2.z, xm2.w};
        float m1[4] = {xm1.x, xm1.y, xm1.z, xm1.w};
        float cc[4] = {x0.x, x0.y, x0.z, x0.w};
        float zv[4] = {zz.x, zz.y, zz.z, zz.w};
        float o[4];
        #pragma unroll
        for (int j = 0; j < 4; j++) {
            float v = fmaf(w0[j], m2[j], fmaf(w1[j], m1[j], fmaf(w2[j], cc[j], cb[j])));
            float u = silu_f(v);
            run[j] += u;
            float y = fmaf(run[j], bc[j], u * dd[j]);
            o[j] = to_tf32(y * silu_f(zv[j]));
        }
        *(float4*)(q + (size_t)t * D_INNER) = make_float4(o[0], o[1], o[2], o[3]);
        xm2 = xm1; xm1 = x0;
    }
}

// ---------------------------------------------------------------------------
// Launch
// ---------------------------------------------------------------------------
extern "C" void kernel_launch(void* const* d_in, const int* in_sizes, int n_in,
                              void* d_out, int out_size)
{
    const float* x      = (const float*)d_in[0];
    const float* W_in   = (const float*)d_in[1];
    const float* conv_w = (const float*)d_in[2];
    const float* conv_b = (const float*)d_in[3];
    const float* Bm     = (const float*)d_in[4];
    const float* Cm     = (const float*)d_in[5];
    const float* Dv     = (const float*)d_in[6];
    const float* W_out  = (const float*)d_in[7];
    float* out = (float*)d_out;

    float* xz;  cudaGetSymbolAddress((void**)&xz, g_XZ);
    float* yz;  cudaGetSymbolAddress((void**)&yz, g_YZ);
    float* wr;  cudaGetSymbolAddress((void**)&wr, g_Wr);
    float* cs;  cudaGetSymbolAddress((void**)&cs, g_CS);

    float* w_in_r  = wr;
    float* w_out_r = wr + (size_t)D_MODEL * N_IN;

    static bool attr_done = false;
    if (!attr_done) {
        cudaFuncSetAttribute(gemm_tf32_kernel<true>,
                             cudaFuncAttributeMaxDynamicSharedMemorySize, GEMM_SMEM_BYTES);
        cudaFuncSetAttribute(gemm_tf32_kernel<false>,
                             cudaFuncAttributeMaxDynamicSharedMemorySize, GEMM_SMEM_BYTES);
        attr_done = true;
    }

    // Pre-round weights only (x is rounded in-register inside GEMM1)
    {
        int n4 = (D_MODEL * N_IN) / 4;
        round_tf32_kernel<<<(n4 + 255) / 256, 256>>>(W_in, w_in_r, n4);
        n4 = (D_INNER * D_MODEL) / 4;
        round_tf32_kernel<<<(n4 + 255) / 256, 256>>>(W_out, w_out_r, n4);
    }

    // GEMM1: xz = round(x) @ W_in_r   [32768,768] x [768,1536]
    {
        dim3 grid(N_IN / BN, M_TOT / BM);
        gemm_tf32_kernel<true><<<grid, 256, GEMM_SMEM_BYTES>>>(
            x, w_in_r, xz, M_TOT, N_IN, D_MODEL);
    }
    // Scan pipeline
    {
        dim3 grid(NCHUNK, BATCH);
        scan_partial_kernel<<<grid, 192>>>(xz, conv_w, conv_b, cs);
        scan_offsets_kernel<<<dim3(D_INNER / 4, BATCH), NCHUNK>>>(cs);
        scan_apply_kernel<<<grid, 192>>>(xz, conv_w, conv_b, Bm, Cm, Dv, cs, yz);
    }
    // GEMM2: out = yz @ W_out_r  [32768,768] x [768,768]
    {
        dim3 grid(D_MODEL / BN, M_TOT / BM);
        gemm_tf32_kernel<false><<<grid, 256, GEMM_SMEM_BYTES>>>(
            yz, w_out_r, out, M_TOT, D_MODEL, D_INNER);
    }
}

// round 11
// speedup vs baseline: 1.4121x; 1.4121x over previous
#include <cuda_runtime.h>
#include <cuda_fp16.h>
#include <cstdint>

// Problem constants
#define D_MODEL 768
#define D_INNER 768
#define D_STATE 8
#define BATCH   4
#define SEQ     8192
#define M_TOT   (BATCH * SEQ)        // 32768
#define N_IN    (2 * D_INNER)        // 1536
#define KDIM    768
#define CHUNK   32
#define NCHUNK  (SEQ / CHUNK)        // 256

// Scratch (static __device__ arrays per allocation rules)
__device__ __half  g_Xh[(size_t)M_TOT * D_MODEL];        // fp16 x
__device__ float   g_XZ[(size_t)M_TOT * N_IN];           // x @ W_in (fp32)
__device__ __half  g_YZh[(size_t)M_TOT * D_INNER];       // fp16 y*silu(z)
__device__ __half2 g_Wp[(size_t)(KDIM / 2) * N_IN + (size_t)(KDIM / 2) * D_MODEL]; // packed W_in | W_out
__device__ float   g_CS[(size_t)BATCH * NCHUNK * D_INNER]; // chunk sums / offsets

// ---------------------------------------------------------------------------
// Conversion kernels
// ---------------------------------------------------------------------------
__global__ __launch_bounds__(256) void convert_x_kernel(
    const float* __restrict__ in, __half* __restrict__ out, int n4)
{
    int i = blockIdx.x * blockDim.x + threadIdx.x;
    if (i >= n4) return;
    float4 v = ((const float4*)in)[i];
    __half2 h0 = __floats2half2_rn(v.x, v.y);
    __half2 h1 = __floats2half2_rn(v.z, v.w);
    ((uint2*)out)[i] = make_uint2(*(uint32_t*)&h0, *(uint32_t*)&h1);
}

// W [K][N] fp32 -> Wp [K/2][N] half2 (k-pair packed)
__global__ __launch_bounds__(256) void pack_w_kernel(
    const float* __restrict__ W, __half2* __restrict__ Wp, int K, int N)
{
    int i = blockIdx.x * blockDim.x + threadIdx.x;
    int total = (K / 2) * N;
    if (i >= total) return;
    int kp = i / N, n = i % N;
    Wp[i] = __floats2half2_rn(W[(size_t)(2 * kp) * N + n],
                              W[(size_t)(2 * kp + 1) * N + n]);
}

// ---------------------------------------------------------------------------
// FP16 tensor-core GEMM: 128x128 blocktile, BK=32, 3-stage cp.async ring.
// 256 threads = 8 warps (4m x 2n); warp tile 32x64; mma.m16n8k16.f16 (fp32 acc).
// A: half row-major [M,K]. Bp: half2 k-pair-packed [K/2][N]. C: fp32 [M,N].
// ---------------------------------------------------------------------------
#define BM 128
#define BN 128
#define BKT 32
#define STAGES 3
#define AH_STRIDE 40                        // 32 + 8 pad halfs (80B rows)
#define BH_STRIDE 136                       // 128 + 8 pad half2 (544B rows)
#define A_STAGE_H (BM * AH_STRIDE)          // 5120 halfs  = 10240 B
#define B_STAGE_H2 ((BKT / 2) * BH_STRIDE)  // 2176 half2 = 8704 B
#define GEMM_SMEM_BYTES (STAGES * (A_STAGE_H * 2 + B_STAGE_H2 * 4))  // 56832

__device__ __forceinline__ void mma_fp16(float* d, const uint32_t* a, const uint32_t* b) {
    asm volatile(
        "mma.sync.aligned.m16n8k16.row.col.f32.f16.f16.f32 "
        "{%0,%1,%2,%3}, {%4,%5,%6,%7}, {%8,%9}, {%0,%1,%2,%3};\n"
        : "+f"(d[0]), "+f"(d[1]), "+f"(d[2]), "+f"(d[3])
        : "r"(a[0]), "r"(a[1]), "r"(a[2]), "r"(a[3]), "r"(b[0]), "r"(b[1]));
}

__device__ __forceinline__ void cpa16(void* dst, const void* src) {
    unsigned d = (unsigned)__cvta_generic_to_shared(dst);
    asm volatile("cp.async.cg.shared.global [%0], [%1], 16;" :: "r"(d), "l"(src) : "memory");
}

__global__ __launch_bounds__(256, 2) void gemm_fp16_kernel(
    const __half* __restrict__ A, const __half2* __restrict__ Bp,
    float* __restrict__ C, int M, int N, int K)
{
    extern __shared__ char smem[];
    __half*  Asm = (__half*)smem;                              // [STAGES][BM][AH_STRIDE]
    __half2* Bsm = (__half2*)(smem + STAGES * A_STAGE_H * 2);  // [STAGES][BKT/2][BH_STRIDE]

    const int tid  = threadIdx.x;
    const int lane = tid & 31;
    const int wid  = tid >> 5;
    const int wm   = wid >> 1;   // 0..3
    const int wn   = wid & 1;    // 0..1
    const int bm   = blockIdx.y;
    const int bn   = blockIdx.x;

    const __half* Ab = A + (size_t)bm * BM * K;
    const __half2* Bb = Bp + (size_t)bn * BN;   // column offset within packed rows

    float acc[2][8][4];
    #pragma unroll
    for (int mi = 0; mi < 2; mi++)
        #pragma unroll
        for (int ni = 0; ni < 8; ni++)
            #pragma unroll
            for (int q = 0; q < 4; q++) acc[mi][ni][q] = 0.0f;

    const int NT = K / BKT;   // 24

    auto load_stage = [&](int kt, int st) {
        __half*  As = Asm + st * A_STAGE_H;
        __half2* Bs = Bsm + st * B_STAGE_H2;
        const int k0 = kt * BKT;
        // A tile 128x32 halfs = 8KB = 512 x 16B, 2 per thread
        #pragma unroll
        for (int i = 0; i < 2; i++) {
            const int idx = tid + i * 256;
            const int r = idx >> 2, c8 = (idx & 3) << 3;   // 8 halfs = 16B
            cpa16(&As[r * AH_STRIDE + c8], Ab + (size_t)r * K + k0 + c8);
        }
        // B tile 16 pair-rows x 128 half2 = 8KB = 512 x 16B, 2 per thread
        #pragma unroll
        for (int i = 0; i < 2; i++) {
            const int idx = tid + i * 256;
            const int pr = idx >> 5, c4 = (idx & 31) << 2; // 4 half2 = 16B
            cpa16(&Bs[pr * BH_STRIDE + c4],
                  Bb + (size_t)(k0 / 2 + pr) * N + c4);
        }
        asm volatile("cp.async.commit_group;" ::: "memory");
    };

    load_stage(0, 0);
    load_stage(1, 1);

    for (int kt = 0; kt < NT; kt++) {
        if (kt + 2 < NT) {
            asm volatile("cp.async.wait_group 1;" ::: "memory");
        } else {
            asm volatile("cp.async.wait_group 0;" ::: "memory");
        }
        __syncthreads();

        if (kt + 2 < NT) load_stage(kt + 2, (kt + 2) % STAGES);

        const __half*  As = Asm + (kt % STAGES) * A_STAGE_H;
        const __half2* Bs = Bsm + (kt % STAGES) * B_STAGE_H2;

        #pragma unroll
        for (int ks2 = 0; ks2 < 2; ks2++) {       // two k16 steps per BKT=32
            const int kbase = ks2 * 16;           // half offset in A rows
            const int prb   = ks2 * 8;            // pair-row offset in B
            uint32_t afr[2][4];
            #pragma unroll
            for (int mi = 0; mi < 2; mi++) {
                const int r = wm * 32 + mi * 16 + (lane >> 2);
                const __half* Ap = As + r * AH_STRIDE + kbase + ((lane & 3) << 1);
                afr[mi][0] = *(const uint32_t*)(Ap);
                afr[mi][1] = *(const uint32_t*)(Ap + 8 * AH_STRIDE);
                afr[mi][2] = *(const uint32_t*)(Ap + 8);
                afr[mi][3] = *(const uint32_t*)(Ap + 8 * AH_STRIDE + 8);
            }
            uint32_t bfr[8][2];
            #pragma unroll
            for (int ni = 0; ni < 8; ni++) {
                const int n = wn * 64 + ni * 8 + (lane >> 2);
                const __half2* Bq = Bs + (prb + (lane & 3)) * BH_STRIDE + n;
                bfr[ni][0] = *(const uint32_t*)(Bq);
                bfr[ni][1] = *(const uint32_t*)(Bq + 4 * BH_STRIDE);
            }
            #pragma unroll
            for (int mi = 0; mi < 2; mi++)
                #pragma unroll
                for (int ni = 0; ni < 8; ni++)
                    mma_fp16(acc[mi][ni], afr[mi], bfr[ni]);
        }
    }

    float* Cb = C + (size_t)bm * BM * N + (size_t)bn * BN;
    #pragma unroll
    for (int mi = 0; mi < 2; mi++) {
        #pragma unroll
        for (int ni = 0; ni < 8; ni++) {
            const int r = wm * 32 + mi * 16 + (lane >> 2);
            const int c = wn * 64 + ni * 8 + ((lane & 3) << 1);
            *(float2*)&Cb[(size_t)r * N + c] =
                make_float2(acc[mi][ni][0], acc[mi][ni][1]);
            *(float2*)&Cb[(size_t)(r + 8) * N + c] =
                make_float2(acc[mi][ni][2], acc[mi][ni][3]);
        }
    }
}

// ---------------------------------------------------------------------------
// silu helper
// ---------------------------------------------------------------------------
__device__ __forceinline__ float silu_f(float v) {
    return v / (1.0f + __expf(-v));
}

// ---------------------------------------------------------------------------
// Pass A: per-chunk sums of u = silu(conv3(xc)+bias). 4 channels per thread.
// ---------------------------------------------------------------------------
__global__ __launch_bounds__(192) void scan_partial_kernel(
    const float* __restrict__ xz,
    const float* __restrict__ convw, const float* __restrict__ convb,
    float* __restrict__ csum)
{
    const int tq = threadIdx.x;
    const int chunk = blockIdx.x;
    const int b = blockIdx.y;
    const int t0 = chunk * CHUNK;
    const int c0 = tq * 4;

    float w0[4], w1[4], w2[4], cb[4];
    #pragma unroll
    for (int j = 0; j < 4; j++) {
        w0[j] = convw[(c0 + j) * 3 + 0];
        w1[j] = convw[(c0 + j) * 3 + 1];
        w2[j] = convw[(c0 + j) * 3 + 2];
        cb[j] = convb[c0 + j];
    }

    const float* p = xz + ((size_t)b * SEQ + t0) * N_IN + c0;

    float4 xm2 = make_float4(0, 0, 0, 0), xm1 = make_float4(0, 0, 0, 0);
    if (t0 >= 2) {
        xm2 = *(const float4*)(p - 2 * N_IN);
        xm1 = *(const float4*)(p - 1 * N_IN);
    }

    float s[4] = {0, 0, 0, 0};
    #pragma unroll 8
    for (int t = 0; t < CHUNK; t++) {
        float4 x0 = *(const float4*)(p + (size_t)t * N_IN);
        float m2[4] = {xm2.x, xm2.y, xm2.z, xm2.w};
        float m1[4] = {xm1.x, xm1.y, xm1.z, xm1.w};
        float cc[4] = {x0.x, x0.y, x0.z, x0.w};
        #pragma unroll
        for (int j = 0; j < 4; j++) {
            float v = fmaf(w0[j], m2[j], fmaf(w1[j], m1[j], fmaf(w2[j], cc[j], cb[j])));
            s[j] += silu_f(v);
        }
        xm2 = xm1; xm1 = x0;
    }
    *(float4*)&csum[((size_t)b * NCHUNK + chunk) * D_INNER + c0] =
        make_float4(s[0], s[1], s[2], s[3]);
}

// ---------------------------------------------------------------------------
// Pass B: block-parallel exclusive scan over NCHUNK chunk sums.
// ---------------------------------------------------------------------------
__global__ __launch_bounds__(NCHUNK) void scan_offsets_kernel(float* __restrict__ csum)
{
    __shared__ float4 sh[NCHUNK];
    const int k = threadIdx.x;
    const int c0 = blockIdx.x * 4;
    const int b = blockIdx.y;

    float4* ptr = (float4*)&csum[((size_t)b * NCHUNK + k) * D_INNER + c0];
    float4 v = *ptr;
    sh[k] = v;
    __syncthreads();

    #pragma unroll
    for (int off = 1; off < NCHUNK; off <<= 1) {
        float4 t = make_float4(0, 0, 0, 0);
        const bool has = (k >= off);
        if (has) t = sh[k - off];
        __syncthreads();
        if (has) {
            v.x += t.x; v.y += t.y; v.z += t.z; v.w += t.w;
            sh[k] = v;
        }
        __syncthreads();
    }
    float4 ex = (k > 0) ? sh[k - 1] : make_float4(0, 0, 0, 0);
    *ptr = ex;
}

// ---------------------------------------------------------------------------
// Pass C: recompute u, y = cum*BC + u*D, times silu(z); write fp16 yz.
// ---------------------------------------------------------------------------
__global__ __launch_bounds__(192) void scan_apply_kernel(
    const float* __restrict__ xz,
    const float* __restrict__ convw, const float* __restrict__ convb,
    const float* __restrict__ Bm, const float* __restrict__ Cm,
    const float* __restrict__ Dv,
    const float* __restrict__ csum,
    __half* __restrict__ yz)
{
    const int tq = threadIdx.x;
    const int chunk = blockIdx.x;
    const int b = blockIdx.y;
    const int t0 = chunk * CHUNK;
    const int c0 = tq * 4;

    float w0[4], w1[4], w2[4], cb[4], bc[4], dd[4];
    #pragma unroll
    for (int j = 0; j < 4; j++) {
        w0[j] = convw[(c0 + j) * 3 + 0];
        w1[j] = convw[(c0 + j) * 3 + 1];
        w2[j] = convw[(c0 + j) * 3 + 2];
        cb[j] = convb[c0 + j];
        float acc = 0.0f;
        #pragma unroll
        for (int s = 0; s < D_STATE; s++)
            acc = fmaf(Bm[(c0 + j) * D_STATE + s], Cm[(c0 + j) * D_STATE + s], acc);
        bc[j] = acc;
        dd[j] = Dv[c0 + j];
    }

    const float* p = xz + ((size_t)b * SEQ + t0) * N_IN + c0;
    __half* q = yz + ((size_t)b * SEQ + t0) * D_INNER + c0;

    float4 xm2 = make_float4(0, 0, 0, 0), xm1 = make_float4(0, 0, 0, 0);
    if (t0 >= 2) {
        xm2 = *(const float4*)(p - 2 * N_IN);
        xm1 = *(const float4*)(p - 1 * N_IN);
    }

    float4 runv = *(const float4*)&csum[((size_t)b * NCHUNK + chunk) * D_INNER + c0];
    float run[4] = {runv.x, runv.y, runv.z, runv.w};

    #pragma unroll 8
    for (int t = 0; t < CHUNK; t++) {
        float4 x0 = *(const float4*)(p + (size_t)t * N_IN);
        float4 zz = *(const float4*)(p + (size_t)t * N_IN + D_INNER);
        float m2[4] = {xm2.x, xm2.y, xm2.z, xm2.w};
        float m1[4] = {xm1.x, xm1.y, xm1.z, xm1.w};
        float cc[4] = {x0.x, x0.y, x0.z, x0.w};
        float zv[4] = {zz.x, zz.y, zz.z, zz.w};
        float o[4];
        #pragma unroll
        for (int j = 0; j < 4; j++) {
            float v = fmaf(w0[j], m2[j], fmaf(w1[j], m1[j], fmaf(w2[j], cc[j], cb[j])));
            float u = silu_f(v);
            run[j] += u;
            float y = fmaf(run[j], bc[j], u * dd[j]);
            o[j] = y * silu_f(zv[j]);
        }
        __half2 h01 = __floats2half2_rn(o[0], o[1]);
        __half2 h23 = __floats2half2_rn(o[2], o[3]);
        *(uint2*)(q + (size_t)t * D_INNER) =
            make_uint2(*(uint32_t*)&h01, *(uint32_t*)&h23);
        xm2 = xm1; xm1 = x0;
    }
}

// ---------------------------------------------------------------------------
// Launch
// ---------------------------------------------------------------------------
extern "C" void kernel_launch(void* const* d_in, const int* in_sizes, int n_in,
                              void* d_out, int out_size)
{
    const float* x      = (const float*)d_in[0];
    const float* W_in   = (const float*)d_in[1];
    const float* conv_w = (const float*)d_in[2];
    const float* conv_b = (const float*)d_in[3];
    const float* Bm     = (const float*)d_in[4];
    const float* Cm     = (const float*)d_in[5];
    const float* Dv     = (const float*)d_in[6];
    const float* W_out  = (const float*)d_in[7];
    float* out = (float*)d_out;

    __half*  xh;  cudaGetSymbolAddress((void**)&xh, g_Xh);
    float*   xz;  cudaGetSymbolAddress((void**)&xz, g_XZ);
    __half*  yzh; cudaGetSymbolAddress((void**)&yzh, g_YZh);
    __half2* wp;  cudaGetSymbolAddress((void**)&wp, g_Wp);
    float*   cs;  cudaGetSymbolAddress((void**)&cs, g_CS);

    __half2* wp_in  = wp;                                // [384][1536]
    __half2* wp_out = wp + (size_t)(KDIM / 2) * N_IN;    // [384][768]

    static bool attr_done = false;
    if (!attr_done) {
        cudaFuncSetAttribute(gemm_fp16_kernel,
                             cudaFuncAttributeMaxDynamicSharedMemorySize, GEMM_SMEM_BYTES);
        attr_done = true;
    }

    // Preprocessing: x -> fp16; weights -> k-pair-packed fp16
    {
        int n4 = (M_TOT * D_MODEL) / 4;
        convert_x_kernel<<<(n4 + 255) / 256, 256>>>(x, xh, n4);
        int t1 = (KDIM / 2) * N_IN;
        pack_w_kernel<<<(t1 + 255) / 256, 256>>>(W_in, wp_in, KDIM, N_IN);
        int t2 = (KDIM / 2) * D_MODEL;
        pack_w_kernel<<<(t2 + 255) / 256, 256>>>(W_out, wp_out, KDIM, D_MODEL);
    }

    // GEMM1: xz = xh @ W_in   [32768,768] x [768,1536]
    {
        dim3 grid(N_IN / BN, M_TOT / BM);
        gemm_fp16_kernel<<<grid, 256, GEMM_SMEM_BYTES>>>(
            xh, wp_in, xz, M_TOT, N_IN, KDIM);
    }
    // Scan pipeline
    {
        dim3 grid(NCHUNK, BATCH);
        scan_partial_kernel<<<grid, 192>>>(xz, conv_w, conv_b, cs);
        scan_offsets_kernel<<<dim3(D_INNER / 4, BATCH), NCHUNK>>>(cs);
        scan_apply_kernel<<<grid, 192>>>(xz, conv_w, conv_b, Bm, Cm, Dv, cs, yzh);
    }
    // GEMM2: out = yzh @ W_out  [32768,768] x [768,768]
    {
        dim3 grid(D_MODEL / BN, M_TOT / BM);
        gemm_fp16_kernel<<<grid, 256, GEMM_SMEM_BYTES>>>(
            yzh, wp_out, out, M_TOT, D_MODEL, KDIM);
    }
}

// round 13
// speedup vs baseline: 2.2575x; 1.5987x over previous
#include <cuda_runtime.h>
#include <cuda_fp16.h>
#include <cstdint>

// Problem constants
#define D_MODEL 768
#define D_INNER 768
#define D_STATE 8
#define BATCH   4
#define SEQ     8192
#define M_TOT   (BATCH * SEQ)        // 32768
#define N_IN    (2 * D_INNER)        // 1536
#define KDIM    768
#define CHUNK   32
#define NCHUNK  (SEQ / CHUNK)        // 256

// Scratch (static __device__ arrays per allocation rules)
__device__ __half g_Xh[(size_t)M_TOT * D_MODEL];         // fp16 x
__device__ float  g_XZ[(size_t)M_TOT * N_IN];            // x @ W_in (fp32)
__device__ __half g_YZh[(size_t)M_TOT * D_INNER];        // fp16 y*silu(z)
__device__ __half g_Wh[(size_t)KDIM * N_IN + (size_t)KDIM * D_MODEL]; // fp16 W_in | W_out
__device__ float  g_CS[(size_t)BATCH * NCHUNK * D_INNER]; // chunk sums / offsets

// ---------------------------------------------------------------------------
// fp32 -> fp16 conversion (used for x and both weights)
// ---------------------------------------------------------------------------
__global__ __launch_bounds__(256) void convert_h_kernel(
    const float* __restrict__ in, __half* __restrict__ out, int n4)
{
    int i = blockIdx.x * blockDim.x + threadIdx.x;
    if (i >= n4) return;
    float4 v = ((const float4*)in)[i];
    __half2 h0 = __floats2half2_rn(v.x, v.y);
    __half2 h1 = __floats2half2_rn(v.z, v.w);
    ((uint2*)out)[i] = make_uint2(*(uint32_t*)&h0, *(uint32_t*)&h1);
}

// ---------------------------------------------------------------------------
// FP16 tensor-core GEMM: 128x128 blocktile, BK=32, 3-stage cp.async ring,
// ldmatrix fragment loads. 256 threads = 8 warps (4m x 2n); warp tile 32x64;
// mma.m16n8k16.f16 with fp32 accumulate.
// A: half row-major [M,K]. Bh: half row-major [K,N]. C: fp32 [M,N].
// ---------------------------------------------------------------------------
#define BM 128
#define BN 128
#define BKT 32
#define STAGES 3
#define AH_STRIDE 40                        // 32 + 8 pad halfs (80B rows)
#define BH_STRIDE 136                       // 128 + 8 pad halfs (272B rows)
#define A_STAGE_H (BM * AH_STRIDE)          // 5120 halfs = 10240 B
#define B_STAGE_H (BKT * BH_STRIDE)         // 4352 halfs = 8704 B
#define GEMM_SMEM_BYTES (STAGES * (A_STAGE_H + B_STAGE_H) * 2)  // 56832

__device__ __forceinline__ void mma_fp16(float* d, const uint32_t* a, const uint32_t* b) {
    asm volatile(
        "mma.sync.aligned.m16n8k16.row.col.f32.f16.f16.f32 "
        "{%0,%1,%2,%3}, {%4,%5,%6,%7}, {%8,%9}, {%0,%1,%2,%3};\n"
        : "+f"(d[0]), "+f"(d[1]), "+f"(d[2]), "+f"(d[3])
        : "r"(a[0]), "r"(a[1]), "r"(a[2]), "r"(a[3]), "r"(b[0]), "r"(b[1]));
}

__device__ __forceinline__ void ldsm_x4(uint32_t* r, uint32_t addr) {
    asm volatile("ldmatrix.sync.aligned.m8n8.x4.shared.b16 {%0,%1,%2,%3}, [%4];"
                 : "=r"(r[0]), "=r"(r[1]), "=r"(r[2]), "=r"(r[3]) : "r"(addr));
}
__device__ __forceinline__ void ldsm_x4_t(uint32_t* r, uint32_t addr) {
    asm volatile("ldmatrix.sync.aligned.m8n8.x4.trans.shared.b16 {%0,%1,%2,%3}, [%4];"
                 : "=r"(r[0]), "=r"(r[1]), "=r"(r[2]), "=r"(r[3]) : "r"(addr));
}

__device__ __forceinline__ void cpa16(void* dst, const void* src) {
    unsigned d = (unsigned)__cvta_generic_to_shared(dst);
    asm volatile("cp.async.cg.shared.global [%0], [%1], 16;" :: "r"(d), "l"(src) : "memory");
}

__global__ __launch_bounds__(256, 2) void gemm_fp16_kernel(
    const __half* __restrict__ A, const __half* __restrict__ Bh,
    float* __restrict__ C, int M, int N, int K)
{
    extern __shared__ char smem[];
    __half* Asm = (__half*)smem;                            // [STAGES][BM][AH_STRIDE]
    __half* Bsm = (__half*)(smem + STAGES * A_STAGE_H * 2); // [STAGES][BKT][BH_STRIDE]

    const int tid  = threadIdx.x;
    const int lane = tid & 31;
    const int wid  = tid >> 5;
    const int wm   = wid >> 1;   // 0..3 -> m offset 32*wm
    const int wn   = wid & 1;    // 0..1 -> n offset 64*wn
    const int bm   = blockIdx.y;
    const int bn   = blockIdx.x;

    const __half* Ab = A + (size_t)bm * BM * K;
    const __half* Bb = Bh + (size_t)bn * BN;

    float acc[2][8][4];
    #pragma unroll
    for (int mi = 0; mi < 2; mi++)
        #pragma unroll
        for (int ni = 0; ni < 8; ni++)
            #pragma unroll
            for (int q = 0; q < 4; q++) acc[mi][ni][q] = 0.0f;

    const int NT = K / BKT;   // 24

    auto load_stage = [&](int kt, int st) {
        __half* As = Asm + st * A_STAGE_H;
        __half* Bs = Bsm + st * B_STAGE_H;
        const int k0 = kt * BKT;
        // A tile 128x32 halfs = 512 x 16B, 2 per thread
        #pragma unroll
        for (int i = 0; i < 2; i++) {
            const int idx = tid + i * 256;
            const int r = idx >> 2, c8 = (idx & 3) << 3;
            cpa16(&As[r * AH_STRIDE + c8], Ab + (size_t)r * K + k0 + c8);
        }
        // B tile 32x128 halfs = 512 x 16B, 2 per thread
        #pragma unroll
        for (int i = 0; i < 2; i++) {
            const int idx = tid + i * 256;
            const int r = idx >> 4, c8 = (idx & 15) << 3;
            cpa16(&Bs[r * BH_STRIDE + c8], Bb + (size_t)(k0 + r) * N + c8);
        }
        asm volatile("cp.async.commit_group;" ::: "memory");
    };

    // ldmatrix per-lane base offsets (bytes)
    const uint32_t asm_u32 = (uint32_t)__cvta_generic_to_shared(Asm);
    const uint32_t bsm_u32 = (uint32_t)__cvta_generic_to_shared(Bsm);
    const uint32_t a_lane = ((wm * 32 + (lane & 15)) * AH_STRIDE + (lane >> 4) * 8) * 2;
    const uint32_t b_lane = (((((lane >> 3) & 1) * 8) + (lane & 7)) * BH_STRIDE
                             + wn * 64 + (lane >> 4) * 8) * 2;

    load_stage(0, 0);
    load_stage(1, 1);

    for (int kt = 0; kt < NT; kt++) {
        if (kt + 2 < NT) {
            asm volatile("cp.async.wait_group 1;" ::: "memory");
        } else {
            asm volatile("cp.async.wait_group 0;" ::: "memory");
        }
        __syncthreads();

        if (kt + 2 < NT) load_stage(kt + 2, (kt + 2) % STAGES);

        const int st = kt % STAGES;
        const uint32_t a_st = asm_u32 + st * A_STAGE_H * 2 + a_lane;
        const uint32_t b_st = bsm_u32 + st * B_STAGE_H * 2 + b_lane;

        #pragma unroll
        for (int ks2 = 0; ks2 < 2; ks2++) {       // two k16 steps per BKT=32
            uint32_t afr[2][4];
            const uint32_t aa = a_st + ks2 * 32;  // +16 halfs
            ldsm_x4(afr[0], aa);
            ldsm_x4(afr[1], aa + 16 * AH_STRIDE * 2);

            uint32_t bfr[8][2];
            #pragma unroll
            for (int ni2 = 0; ni2 < 4; ni2++) {   // 2 n8-groups per LDSM
                uint32_t r[4];
                ldsm_x4_t(r, b_st + ks2 * 16 * BH_STRIDE * 2 + ni2 * 32);
                bfr[2 * ni2][0] = r[0]; bfr[2 * ni2][1] = r[1];
                bfr[2 * ni2 + 1][0] = r[2]; bfr[2 * ni2 + 1][1] = r[3];
            }
            #pragma unroll
            for (int mi = 0; mi < 2; mi++)
                #pragma unroll
                for (int ni = 0; ni < 8; ni++)
                    mma_fp16(acc[mi][ni], afr[mi], bfr[ni]);
        }
    }

    float* Cb = C + (size_t)bm * BM * N + (size_t)bn * BN;
    #pragma unroll
    for (int mi = 0; mi < 2; mi++) {
        #pragma unroll
        for (int ni = 0; ni < 8; ni++) {
            const int r = wm * 32 + mi * 16 + (lane >> 2);
            const int c = wn * 64 + ni * 8 + ((lane & 3) << 1);
            *(float2*)&Cb[(size_t)r * N + c] =
                make_float2(acc[mi][ni][0], acc[mi][ni][1]);
            *(float2*)&Cb[(size_t)(r + 8) * N + c] =
                make_float2(acc[mi][ni][2], acc[mi][ni][3]);
        }
    }
}

// ---------------------------------------------------------------------------
// silu helper
// ---------------------------------------------------------------------------
__device__ __forceinline__ float silu_f(float v) {
    return v / (1.0f + __expf(-v));
}

// ---------------------------------------------------------------------------
// Pass A: per-chunk sums of u = silu(conv3(xc)+bias). 4 channels per thread.
// ---------------------------------------------------------------------------
__global__ __launch_bounds__(192) void scan_partial_kernel(
    const float* __restrict__ xz,
    const float* __restrict__ convw, const float* __restrict__ convb,
    float* __restrict__ csum)
{
    const int tq = threadIdx.x;
    const int chunk = blockIdx.x;
    const int b = blockIdx.y;
    const int t0 = chunk * CHUNK;
    const int c0 = tq * 4;

    float w0[4], w1[4], w2[4], cb[4];
    #pragma unroll
    for (int j = 0; j < 4; j++) {
        w0[j] = convw[(c0 + j) * 3 + 0];
        w1[j] = convw[(c0 + j) * 3 + 1];
        w2[j] = convw[(c0 + j) * 3 + 2];
        cb[j] = convb[c0 + j];
    }

    const float* p = xz + ((size_t)b * SEQ + t0) * N_IN + c0;

    float4 xm2 = make_float4(0, 0, 0, 0), xm1 = make_float4(0, 0, 0, 0);
    if (t0 >= 2) {
        xm2 = *(const float4*)(p - 2 * N_IN);
        xm1 = *(const float4*)(p - 1 * N_IN);
    }

    float s[4] = {0, 0, 0, 0};
    #pragma unroll 8
    for (int t = 0; t < CHUNK; t++) {
        float4 x0 = *(const float4*)(p + (size_t)t * N_IN);
        float m2[4] = {xm2.x, xm2.y, xm2.z, xm2.w};
        float m1[4] = {xm1.x, xm1.y, xm1.z, xm1.w};
        float cc[4] = {x0.x, x0.y, x0.z, x0.w};
        #pragma unroll
        for (int j = 0; j < 4; j++) {
            float v = fmaf(w0[j], m2[j], fmaf(w1[j], m1[j], fmaf(w2[j], cc[j], cb[j])));
            s[j] += silu_f(v);
        }
        xm2 = xm1; xm1 = x0;
    }
    *(float4*)&csum[((size_t)b * NCHUNK + chunk) * D_INNER + c0] =
        make_float4(s[0], s[1], s[2], s[3]);
}

// ---------------------------------------------------------------------------
// Pass B: block-parallel exclusive scan over NCHUNK chunk sums.
// ---------------------------------------------------------------------------
__global__ __launch_bounds__(NCHUNK) void scan_offsets_kernel(float* __restrict__ csum)
{
    __shared__ float4 sh[NCHUNK];
    const int k = threadIdx.x;
    const int c0 = blockIdx.x * 4;
    const int b = blockIdx.y;

    float4* ptr = (float4*)&csum[((size_t)b * NCHUNK + k) * D_INNER + c0];
    float4 v = *ptr;
    sh[k] = v;
    __syncthreads();

    #pragma unroll
    for (int off = 1; off < NCHUNK; off <<= 1) {
        float4 t = make_float4(0, 0, 0, 0);
        const bool has = (k >= off);
        if (has) t = sh[k - off];
        __syncthreads();
        if (has) {
            v.x += t.x; v.y += t.y; v.z += t.z; v.w += t.w;
            sh[k] = v;
        }
        __syncthreads();
    }
    float4 ex = (k > 0) ? sh[k - 1] : make_float4(0, 0, 0, 0);
    *ptr = ex;
}

// ---------------------------------------------------------------------------
// Pass C: recompute u, y = cum*BC + u*D, times silu(z); write fp16 yz.
// ---------------------------------------------------------------------------
__global__ __launch_bounds__(192) void scan_apply_kernel(
    const float* __restrict__ xz,
    const float* __restrict__ convw, const float* __restrict__ convb,
    const float* __restrict__ Bm, const float* __restrict__ Cm,
    const float* __restrict__ Dv,
    const float* __restrict__ csum,
    __half* __restrict__ yz)
{
    const int tq = threadIdx.x;
    const int chunk = blockIdx.x;
    const int b = blockIdx.y;
    const int t0 = chunk * CHUNK;
    const int c0 = tq * 4;

    float w0[4], w1[4], w2[4], cb[4], bc[4], dd[4];
    #pragma unroll
    for (int j = 0; j < 4; j++) {
        w0[j] = convw[(c0 + j) * 3 + 0];
        w1[j] = convw[(c0 + j) * 3 + 1];
        w2[j] = convw[(c0 + j) * 3 + 2];
        cb[j] = convb[c0 + j];
        float acc = 0.0f;
        #pragma unroll
        for (int s = 0; s < D_STATE; s++)
            acc = fmaf(Bm[(c0 + j) * D_STATE + s], Cm[(c0 + j) * D_STATE + s], acc);
        bc[j] = acc;
        dd[j] = Dv[c0 + j];
    }

    const float* p = xz + ((size_t)b * SEQ + t0) * N_IN + c0;
    __half* q = yz + ((size_t)b * SEQ + t0) * D_INNER + c0;

    float4 xm2 = make_float4(0, 0, 0, 0), xm1 = make_float4(0, 0, 0, 0);
    if (t0 >= 2) {
        xm2 = *(const float4*)(p - 2 * N_IN);
        xm1 = *(const float4*)(p - 1 * N_IN);
    }

    float4 runv = *(const float4*)&csum[((size_t)b * NCHUNK + chunk) * D_INNER + c0];
    float run[4] = {runv.x, runv.y, runv.z, runv.w};

    #pragma unroll 8
    for (int t = 0; t < CHUNK; t++) {
        float4 x0 = *(const float4*)(p + (size_t)t * N_IN);
        float4 zz = *(const float4*)(p + (size_t)t * N_IN + D_INNER);
        float m2[4] = {xm2.x, xm2.y, xm2.z, xm2.w};
        float m1[4] = {xm1.x, xm1.y, xm1.z, xm1.w};
        float cc[4] = {x0.x, x0.y, x0.z, x0.w};
        float zv[4] = {zz.x, zz.y, zz.z, zz.w};
        float o[4];
        #pragma unroll
        for (int j = 0; j < 4; j++) {
            float v = fmaf(w0[j], m2[j], fmaf(w1[j], m1[j], fmaf(w2[j], cc[j], cb[j])));
            float u = silu_f(v);
            run[j] += u;
            float y = fmaf(run[j], bc[j], u * dd[j]);
            o[j] = y * silu_f(zv[j]);
        }
        __half2 h01 = __floats2half2_rn(o[0], o[1]);
        __half2 h23 = __floats2half2_rn(o[2], o[3]);
        *(uint2*)(q + (size_t)t * D_INNER) =
            make_uint2(*(uint32_t*)&h01, *(uint32_t*)&h23);
        xm2 = xm1; xm1 = x0;
    }
}

// ---------------------------------------------------------------------------
// Launch
// ---------------------------------------------------------------------------
extern "C" void kernel_launch(void* const* d_in, const int* in_sizes, int n_in,
                              void* d_out, int out_size)
{
    const float* x      = (const float*)d_in[0];
    const float* W_in   = (const float*)d_in[1];
    const float* conv_w = (const float*)d_in[2];
    const float* conv_b = (const float*)d_in[3];
    const float* Bm     = (const float*)d_in[4];
    const float* Cm     = (const float*)d_in[5];
    const float* Dv     = (const float*)d_in[6];
    const float* W_out  = (const float*)d_in[7];
    float* out = (float*)d_out;

    __half* xh;  cudaGetSymbolAddress((void**)&xh, g_Xh);
    float*  xz;  cudaGetSymbolAddress((void**)&xz, g_XZ);
    __half* yzh; cudaGetSymbolAddress((void**)&yzh, g_YZh);
    __half* wh;  cudaGetSymbolAddress((void**)&wh, g_Wh);
    float*  cs;  cudaGetSymbolAddress((void**)&cs, g_CS);

    __half* wh_in  = wh;                             // [768][1536]
    __half* wh_out = wh + (size_t)KDIM * N_IN;       // [768][768]

    static bool attr_done = false;
    if (!attr_done) {
        cudaFuncSetAttribute(gemm_fp16_kernel,
                             cudaFuncAttributeMaxDynamicSharedMemorySize, GEMM_SMEM_BYTES);
        attr_done = true;
    }

    // Preprocessing: x and weights -> fp16
    {
        int n4 = (M_TOT * D_MODEL) / 4;
        convert_h_kernel<<<(n4 + 255) / 256, 256>>>(x, xh, n4);
        n4 = (KDIM * N_IN) / 4;
        convert_h_kernel<<<(n4 + 255) / 256, 256>>>(W_in, wh_in, n4);
        n4 = (KDIM * D_MODEL) / 4;
        convert_h_kernel<<<(n4 + 255) / 256, 256>>>(W_out, wh_out, n4);
    }

    // GEMM1: xz = xh @ W_in   [32768,768] x [768,1536]
    {
        dim3 grid(N_IN / BN, M_TOT / BM);
        gemm_fp16_kernel<<<grid, 256, GEMM_SMEM_BYTES>>>(
            xh, wh_in, xz, M_TOT, N_IN, KDIM);
    }
    // Scan pipeline
    {
        dim3 grid(NCHUNK, BATCH);
        scan_partial_kernel<<<grid, 192>>>(xz, conv_w, conv_b, cs);
        scan_offsets_kernel<<<dim3(D_INNER / 4, BATCH), NCHUNK>>>(cs);
        scan_apply_kernel<<<grid, 192>>>(xz, conv_w, conv_b, Bm, Cm, Dv, cs, yzh);
    }
    // GEMM2: out = yzh @ W_out  [32768,768] x [768,768]
    {
        dim3 grid(D_MODEL / BN, M_TOT / BM);
        gemm_fp16_kernel<<<grid, 256, GEMM_SMEM_BYTES>>>(
            yzh, wh_out, out, M_TOT, D_MODEL, KDIM);
    }
}